// round 2
// baseline (speedup 1.0000x reference)
#include <cuda_runtime.h>
#include <math.h>

#define NB 32
#define LL 1024
#define DD 256
#define HH 256

// Scratch (device globals; no allocations allowed)
__device__ float g_Fp[(size_t)NB * LL * HH];   // 32 MB
__device__ float g_Fh[(size_t)NB * LL * HH];   // 32 MB
__device__ float g_E [(size_t)NB * LL * LL];   // 134 MB
__device__ float g_rowmax[NB * LL];
__device__ float g_rowsum[NB * LL];
__device__ float g_colmax[NB * LL];
__device__ float g_colsum[NB * LL];

// ---------------------------------------------------------------------------
// K1: F = tanh(X @ W), X:[M,256] row-major, W:[256,256] row-major, F:[M,256]
// 64x64 block tile, BK=16, 256 threads, 4x4 per thread.
// ---------------------------------------------------------------------------
__global__ void proj_tanh_kernel(const float* __restrict__ X,
                                 const float* __restrict__ W,
                                 int which) {
    float* F = which ? g_Fh : g_Fp;
    __shared__ __align__(16) float As[16][68];  // As[k][m]
    __shared__ __align__(16) float Bs[16][68];  // Bs[k][n]
    const int bm = blockIdx.x * 64;
    const int bn = blockIdx.y * 64;
    const int tid = threadIdx.x;
    const int tx = tid & 15, ty = tid >> 4;
    float acc[4][4] = {};
    for (int k0 = 0; k0 < DD; k0 += 16) {
        #pragma unroll
        for (int i = tid; i < 64 * 16; i += 256) {
            int m = i >> 4, k = i & 15;
            As[k][m] = X[(size_t)(bm + m) * DD + k0 + k];
        }
        #pragma unroll
        for (int i = tid; i < 16 * 64; i += 256) {
            int k = i >> 6, n = i & 63;
            Bs[k][n] = W[(size_t)(k0 + k) * HH + bn + n];
        }
        __syncthreads();
        #pragma unroll
        for (int k = 0; k < 16; k++) {
            float4 av = *(const float4*)&As[k][ty * 4];
            float4 bv = *(const float4*)&Bs[k][tx * 4];
            float a[4] = {av.x, av.y, av.z, av.w};
            float b[4] = {bv.x, bv.y, bv.z, bv.w};
            #pragma unroll
            for (int i = 0; i < 4; i++)
                #pragma unroll
                for (int j = 0; j < 4; j++)
                    acc[i][j] += a[i] * b[j];
        }
        __syncthreads();
    }
    #pragma unroll
    for (int i = 0; i < 4; i++)
        #pragma unroll
        for (int j = 0; j < 4; j++)
            F[(size_t)(bm + ty * 4 + i) * HH + bn + tx * 4 + j] = tanhf(acc[i][j]);
}

// ---------------------------------------------------------------------------
// K2: E[b] = Fp[b] @ Fh[b]^T   (NT GEMM, 1024x1024x256 per batch)
// ---------------------------------------------------------------------------
__global__ void eij_kernel() {
    const int b = blockIdx.z;
    const float* A = g_Fp + (size_t)b * LL * HH;
    const float* Bm = g_Fh + (size_t)b * LL * HH;
    float* E = g_E + (size_t)b * LL * LL;
    __shared__ __align__(16) float As[16][68];
    __shared__ __align__(16) float Bs[16][68];
    const int bm = blockIdx.x * 64;
    const int bn = blockIdx.y * 64;
    const int tid = threadIdx.x;
    const int tx = tid & 15, ty = tid >> 4;
    float acc[4][4] = {};
    for (int k0 = 0; k0 < HH; k0 += 16) {
        #pragma unroll
        for (int i = tid; i < 64 * 16; i += 256) {
            int m = i >> 4, k = i & 15;
            As[k][m] = A[(size_t)(bm + m) * HH + k0 + k];
        }
        #pragma unroll
        for (int i = tid; i < 64 * 16; i += 256) {
            int n = i >> 4, k = i & 15;
            Bs[k][n] = Bm[(size_t)(bn + n) * HH + k0 + k];
        }
        __syncthreads();
        #pragma unroll
        for (int k = 0; k < 16; k++) {
            float4 av = *(const float4*)&As[k][ty * 4];
            float4 bv = *(const float4*)&Bs[k][tx * 4];
            float a[4] = {av.x, av.y, av.z, av.w};
            float b2[4] = {bv.x, bv.y, bv.z, bv.w};
            #pragma unroll
            for (int i = 0; i < 4; i++)
                #pragma unroll
                for (int j = 0; j < 4; j++)
                    acc[i][j] += a[i] * b2[j];
        }
        __syncthreads();
    }
    #pragma unroll
    for (int i = 0; i < 4; i++)
        #pragma unroll
        for (int j = 0; j < 4; j++)
            E[(size_t)(bm + ty * 4 + i) * LL + bn + tx * 4 + j] = acc[i][j];
}

// ---------------------------------------------------------------------------
// K3a: per-row (axis=q) max & sum(exp) over E. One block per (b,p) row.
// ---------------------------------------------------------------------------
__global__ void rowstats_kernel() {
    const size_t r = blockIdx.x;           // b*LL + p
    const float* row = g_E + r * LL;
    const int t = threadIdx.x;
    float v0 = row[t], v1 = row[t + 256], v2 = row[t + 512], v3 = row[t + 768];
    float m = fmaxf(fmaxf(v0, v1), fmaxf(v2, v3));
    __shared__ float red[256];
    red[t] = m; __syncthreads();
    #pragma unroll
    for (int s = 128; s > 0; s >>= 1) {
        if (t < s) red[t] = fmaxf(red[t], red[t + s]);
        __syncthreads();
    }
    float M = red[0];
    __syncthreads();
    float s = __expf(v0 - M) + __expf(v1 - M) + __expf(v2 - M) + __expf(v3 - M);
    red[t] = s; __syncthreads();
    #pragma unroll
    for (int st = 128; st > 0; st >>= 1) {
        if (t < st) red[t] += red[t + st];
        __syncthreads();
    }
    if (t == 0) { g_rowmax[r] = M; g_rowsum[r] = red[0]; }
}

// ---------------------------------------------------------------------------
// K3b: per-column (axis=p) online max & sum(exp). Block = (b, 64 columns).
// ---------------------------------------------------------------------------
__global__ void colstats_kernel() {
    const int b = blockIdx.y;
    const int c0 = blockIdx.x * 64;
    const int t = threadIdx.x;
    const int c = t & 63, pr = t >> 6;
    const float* E = g_E + (size_t)b * LL * LL;
    float m = -INFINITY, s = 0.f;
    for (int p = pr; p < LL; p += 4) {
        float v = E[(size_t)p * LL + c0 + c];
        float mn = fmaxf(m, v);
        s = s * __expf(m - mn) + __expf(v - mn);
        m = mn;
    }
    __shared__ float sm[256], ss[256];
    sm[t] = m; ss[t] = s; __syncthreads();
    if (t < 64) {
        float M = sm[t], S = ss[t];
        #pragma unroll
        for (int i = 1; i < 4; i++) {
            float m2 = sm[t + i * 64], s2 = ss[t + i * 64];
            float Mn = fmaxf(M, m2);
            S = S * __expf(M - Mn) + s2 * __expf(m2 - Mn);
            M = Mn;
        }
        g_colmax[b * LL + c0 + c] = M;
        g_colsum[b * LL + c0 + c] = S;
    }
}

// ---------------------------------------------------------------------------
// K4: betas[b,p,d] = sum_q exp(E[b,p,q]-rowmax)/rowsum * Hyp[b,q,d]
// exp fused into the A-tile smem load. NN GEMM 1024x256x1024 per batch.
// ---------------------------------------------------------------------------
__global__ void betas_kernel(const float* __restrict__ Hyp, float* __restrict__ out) {
    const int b = blockIdx.z;
    const int bm = blockIdx.x * 64;   // p
    const int bn = blockIdx.y * 64;   // d
    const float* E = g_E + (size_t)b * LL * LL;
    const float* Bm = Hyp + (size_t)b * LL * DD;
    __shared__ __align__(16) float As[16][68];
    __shared__ __align__(16) float Bs[16][68];
    __shared__ float rmax[64], rsum[64];
    const int tid = threadIdx.x;
    const int tx = tid & 15, ty = tid >> 4;
    if (tid < 64) {
        rmax[tid] = g_rowmax[b * LL + bm + tid];
        rsum[tid] = g_rowsum[b * LL + bm + tid];
    }
    __syncthreads();
    float acc[4][4] = {};
    for (int k0 = 0; k0 < LL; k0 += 16) {
        #pragma unroll
        for (int i = tid; i < 64 * 16; i += 256) {
            int m = i >> 4, k = i & 15;
            As[k][m] = __expf(E[(size_t)(bm + m) * LL + k0 + k] - rmax[m]);
        }
        #pragma unroll
        for (int i = tid; i < 16 * 64; i += 256) {
            int k = i >> 6, n = i & 63;
            Bs[k][n] = Bm[(size_t)(k0 + k) * DD + bn + n];
        }
        __syncthreads();
        #pragma unroll
        for (int k = 0; k < 16; k++) {
            float4 av = *(const float4*)&As[k][ty * 4];
            float4 bv = *(const float4*)&Bs[k][tx * 4];
            float a[4] = {av.x, av.y, av.z, av.w};
            float b2[4] = {bv.x, bv.y, bv.z, bv.w};
            #pragma unroll
            for (int i = 0; i < 4; i++)
                #pragma unroll
                for (int j = 0; j < 4; j++)
                    acc[i][j] += a[i] * b2[j];
        }
        __syncthreads();
    }
    #pragma unroll
    for (int i = 0; i < 4; i++) {
        float inv = 1.0f / rsum[ty * 4 + i];
        #pragma unroll
        for (int j = 0; j < 4; j++)
            out[(size_t)(b * LL + bm + ty * 4 + i) * DD + bn + tx * 4 + j] = acc[i][j] * inv;
    }
}

// ---------------------------------------------------------------------------
// K5: alphas[b,q,d] = sum_p exp(E[b,p,q]-colmax)/colsum * Prem[b,p,d]
// A-tile read from E with transpose (coalesced rows -> As[k][q]).
// ---------------------------------------------------------------------------
__global__ void alphas_kernel(const float* __restrict__ Prem, float* __restrict__ out) {
    const int b = blockIdx.z;
    const int bm = blockIdx.x * 64;   // q
    const int bn = blockIdx.y * 64;   // d
    const float* E = g_E + (size_t)b * LL * LL;
    const float* Bm = Prem + (size_t)b * LL * DD;
    __shared__ __align__(16) float As[16][68];
    __shared__ __align__(16) float Bs[16][68];
    __shared__ float cmax[64], csum[64];
    const int tid = threadIdx.x;
    const int tx = tid & 15, ty = tid >> 4;
    if (tid < 64) {
        cmax[tid] = g_colmax[b * LL + bm + tid];
        csum[tid] = g_colsum[b * LL + bm + tid];
    }
    __syncthreads();
    float acc[4][4] = {};
    for (int k0 = 0; k0 < LL; k0 += 16) {   // k = p
        #pragma unroll
        for (int i = tid; i < 16 * 64; i += 256) {
            int k = i >> 6, m = i & 63;
            As[k][m] = __expf(E[(size_t)(k0 + k) * LL + bm + m] - cmax[m]);
        }
        #pragma unroll
        for (int i = tid; i < 16 * 64; i += 256) {
            int k = i >> 6, n = i & 63;
            Bs[k][n] = Bm[(size_t)(k0 + k) * DD + bn + n];
        }
        __syncthreads();
        #pragma unroll
        for (int k = 0; k < 16; k++) {
            float4 av = *(const float4*)&As[k][ty * 4];
            float4 bv = *(const float4*)&Bs[k][tx * 4];
            float a[4] = {av.x, av.y, av.z, av.w};
            float b2[4] = {bv.x, bv.y, bv.z, bv.w};
            #pragma unroll
            for (int i = 0; i < 4; i++)
                #pragma unroll
                for (int j = 0; j < 4; j++)
                    acc[i][j] += a[i] * b2[j];
        }
        __syncthreads();
    }
    #pragma unroll
    for (int i = 0; i < 4; i++) {
        float inv = 1.0f / csum[ty * 4 + i];
        #pragma unroll
        for (int j = 0; j < 4; j++)
            out[(size_t)(b * LL + bm + ty * 4 + i) * DD + bn + tx * 4 + j] = acc[i][j] * inv;
    }
}

// ---------------------------------------------------------------------------
extern "C" void kernel_launch(void* const* d_in, const int* in_sizes, int n_in,
                              void* d_out, int out_size) {
    const float* P   = (const float*)d_in[0];   // premises  [32,1024,256]
    const float* Hyp = (const float*)d_in[1];   // hypotheses[32,1024,256]
    const float* W   = (const float*)d_in[2];   // W_F [256,256]
    float* out = (float*)d_out;

    dim3 t(256);
    proj_tanh_kernel<<<dim3(512, 4), t>>>(P, W, 0);
    proj_tanh_kernel<<<dim3(512, 4), t>>>(Hyp, W, 1);
    eij_kernel<<<dim3(16, 16, NB), t>>>();
    rowstats_kernel<<<NB * LL, t>>>();
    colstats_kernel<<<dim3(16, NB), t>>>();
    betas_kernel<<<dim3(16, 4, NB), t>>>(Hyp, out);
    alphas_kernel<<<dim3(16, 4, NB), t>>>(P, out + (size_t)NB * LL * DD);
}

// round 4
// speedup vs baseline: 2.3898x; 2.3898x over previous
#include <cuda_runtime.h>
#include <cuda_bf16.h>
#include <math.h>
#include <stdint.h>

#define NB 32
#define LL 1024
#define DD 256
#define HH 256
typedef __nv_bfloat16 bf16;

// ---------------------------------------------------------------------------
// Device scratch (no allocations allowed)
// ---------------------------------------------------------------------------
#define NXD ((size_t)NB * LL * DD)      // 8,388,608
#define NE  ((size_t)NB * LL * LL)      // 33,554,432

__device__ __align__(256) bf16 g_Xp_hi[NXD], g_Xp_lo[NXD];
__device__ __align__(256) bf16 g_Xh_hi[NXD], g_Xh_lo[NXD];
__device__ __align__(256) bf16 g_Wt_hi[DD * HH], g_Wt_lo[DD * HH];
__device__ __align__(256) bf16 g_Fp_hi[NXD], g_Fp_lo[NXD];
__device__ __align__(256) bf16 g_Fh_hi[NXD], g_Fh_lo[NXD];
__device__ __align__(256) bf16 g_Ht_hi[NXD], g_Ht_lo[NXD];
__device__ __align__(256) bf16 g_Pt_hi[NXD], g_Pt_lo[NXD];
__device__ __align__(256) float g_E[NE];
__device__ __align__(256) float g_Et[NE];
__device__ __align__(256) bf16 g_Tr_hi[NE], g_Tr_lo[NE];
__device__ __align__(256) bf16 g_Tc_hi[NE], g_Tc_lo[NE];
__device__ __align__(256) float g_rowmax[NB * LL], g_rowsum[NB * LL];
__device__ __align__(256) float g_colmax[NB * LL], g_colsum[NB * LL];

// ---------------------------------------------------------------------------
// warp-mma helpers (sm_80-class, no 'a' suffix features)
// ---------------------------------------------------------------------------
__device__ __forceinline__ uint32_t smem_u32(const void* p) {
    uint32_t a;
    asm("{ .reg .u64 t; cvta.to.shared.u64 t, %1; cvt.u32.u64 %0, t; }" : "=r"(a) : "l"(p));
    return a;
}
__device__ __forceinline__ void ldsm4(uint32_t& r0, uint32_t& r1, uint32_t& r2,
                                      uint32_t& r3, uint32_t addr) {
    asm volatile("ldmatrix.sync.aligned.m8n8.x4.shared.b16 {%0,%1,%2,%3}, [%4];"
                 : "=r"(r0), "=r"(r1), "=r"(r2), "=r"(r3) : "r"(addr));
}
__device__ __forceinline__ void mma_bf16(float* c, const uint32_t* a, uint32_t b0, uint32_t b1) {
    asm volatile(
        "mma.sync.aligned.m16n8k16.row.col.f32.bf16.bf16.f32 "
        "{%0,%1,%2,%3}, {%4,%5,%6,%7}, {%8,%9}, {%0,%1,%2,%3};"
        : "+f"(c[0]), "+f"(c[1]), "+f"(c[2]), "+f"(c[3])
        : "r"(a[0]), "r"(a[1]), "r"(a[2]), "r"(a[3]), "r"(b0), "r"(b1));
}

// ---------------------------------------------------------------------------
// Split-bf16 warp-MMA GEMM: C[m,n] = sum_k A[m,k]*B[n,k]
// A = Ahi+Alo, B = Bhi+Blo: 3 passes (hh, hi*lo, lo*hi) accumulated in regs.
// CTA tile 128x128, BK=32, 8 warps (4m x 2n), warp tile 32x64.
// epi: 0 = store fp32 C; 1 = tanh -> split bf16 (Fhi/Flo); 2 = scale by
//      1/scale[b*mpb+m] then store fp32 C.
// ---------------------------------------------------------------------------
__global__ __launch_bounds__(256) void gemm_split(
    const bf16* __restrict__ Ahi, const bf16* __restrict__ Alo, size_t a_bs, int lda,
    const bf16* __restrict__ Bhi, const bf16* __restrict__ Blo, size_t b_bs, int ldb,
    int K, int epi,
    float* __restrict__ C, size_t c_bs, int ldc,
    const float* __restrict__ scale, int mpb,
    bf16* __restrict__ Fhi, bf16* __restrict__ Flo)
{
    // pitch 40 bf16 (80B): bank16 index = 5*row + chunk (mod 8), conflict-free
    __shared__ __align__(16) bf16 sA[128 * 40];
    __shared__ __align__(16) bf16 sB[128 * 40];
    const uint32_t sAb = smem_u32(sA);
    const uint32_t sBb = smem_u32(sB);

    const int tid = threadIdx.x;
    const int lane = tid & 31;
    const int wid = tid >> 5;
    const int wm = wid & 3;          // warp row  (x32)
    const int wn = wid >> 2;         // warp col  (x64)
    const int bm = blockIdx.x * 128;
    const int bn = blockIdx.y * 128;
    const int b  = blockIdx.z;

    const int nk = K >> 5;           // BK=32 chunks per pass
    const int nch = 3 * nk;

    // per-thread global-load coords (2 uint4 per tile)
    const int r0 = tid >> 2, kv0 = (tid & 3) * 8;
    const int r1 = (tid + 256) >> 2, kv1 = ((tid + 256) & 3) * 8;

    float acc[2][8][4] = {};

    // ---- preload chunk 0
    {
        const bf16* Ap = Ahi + (size_t)b * a_bs;
        const bf16* Bp = Bhi + (size_t)b * b_bs;
        *(uint4*)(sA + r0 * 40 + kv0) = *(const uint4*)(Ap + (size_t)(bm + r0) * lda + kv0);
        *(uint4*)(sA + r1 * 40 + kv1) = *(const uint4*)(Ap + (size_t)(bm + r1) * lda + kv1);
        *(uint4*)(sB + r0 * 40 + kv0) = *(const uint4*)(Bp + (size_t)(bn + r0) * ldb + kv0);
        *(uint4*)(sB + r1 * 40 + kv1) = *(const uint4*)(Bp + (size_t)(bn + r1) * ldb + kv1);
    }
    __syncthreads();

    for (int ch = 0; ch < nch; ch++) {
        // ---- prefetch next chunk into registers
        uint4 pa0, pa1, pb0, pb1;
        const bool more = (ch + 1 < nch);
        if (more) {
            const int nc = ch + 1;
            const int pass = nc / nk;
            const int k0 = (nc - pass * nk) << 5;
            const bf16* Ap = (pass == 2 ? Alo : Ahi) + (size_t)b * a_bs;
            const bf16* Bp = (pass == 1 ? Blo : Bhi) + (size_t)b * b_bs;
            pa0 = *(const uint4*)(Ap + (size_t)(bm + r0) * lda + k0 + kv0);
            pa1 = *(const uint4*)(Ap + (size_t)(bm + r1) * lda + k0 + kv1);
            pb0 = *(const uint4*)(Bp + (size_t)(bn + r0) * ldb + k0 + kv0);
            pb1 = *(const uint4*)(Bp + (size_t)(bn + r1) * ldb + k0 + kv1);
        }

        // ---- compute from smem: 2 k-steps of k16
        #pragma unroll
        for (int ks = 0; ks < 2; ks++) {
            const uint32_t colb = (uint32_t)(ks * 16 + (lane >> 4) * 8) * 2;
            uint32_t a[2][4];
            #pragma unroll
            for (int fm = 0; fm < 2; fm++) {
                uint32_t ad = sAb + (uint32_t)(wm * 32 + fm * 16 + (lane & 15)) * 80 + colb;
                ldsm4(a[fm][0], a[fm][1], a[fm][2], a[fm][3], ad);
            }
            uint32_t bb[4][4];
            #pragma unroll
            for (int fn = 0; fn < 4; fn++) {
                uint32_t bd = sBb + (uint32_t)(wn * 64 + fn * 16 + (lane & 15)) * 80 + colb;
                ldsm4(bb[fn][0], bb[fn][1], bb[fn][2], bb[fn][3], bd);
            }
            #pragma unroll
            for (int fm = 0; fm < 2; fm++)
                #pragma unroll
                for (int fn = 0; fn < 4; fn++) {
                    mma_bf16(acc[fm][fn * 2],     a[fm], bb[fn][0], bb[fn][2]);
                    mma_bf16(acc[fm][fn * 2 + 1], a[fm], bb[fn][1], bb[fn][3]);
                }
        }
        __syncthreads();
        if (more) {
            *(uint4*)(sA + r0 * 40 + kv0) = pa0;
            *(uint4*)(sA + r1 * 40 + kv1) = pa1;
            *(uint4*)(sB + r0 * 40 + kv0) = pb0;
            *(uint4*)(sB + r1 * 40 + kv1) = pb1;
            __syncthreads();
        }
    }

    // ---- epilogue.  acc frag (m16n8): c0,c1 @ row=lane/4, cols 2*(lane%4)+{0,1};
    //                 c2,c3 @ row+8.
    const int fr = lane >> 2;
    const int fc = (lane & 3) * 2;
    #pragma unroll
    for (int fm = 0; fm < 2; fm++) {
        const int row0 = bm + wm * 32 + fm * 16 + fr;
        if (epi == 1) {
            #pragma unroll
            for (int half = 0; half < 2; half++) {
                const size_t gr = (size_t)(row0 + half * 8);
                #pragma unroll
                for (int fn = 0; fn < 8; fn++) {
                    const int col = bn + wn * 64 + fn * 8 + fc;
                    float v0 = tanhf(acc[fm][fn][half * 2]);
                    float v1 = tanhf(acc[fm][fn][half * 2 + 1]);
                    bf16 h0 = __float2bfloat16(v0), h1 = __float2bfloat16(v1);
                    __nv_bfloat162 hp, lp;
                    hp.x = h0; hp.y = h1;
                    lp.x = __float2bfloat16(v0 - __bfloat162float(h0));
                    lp.y = __float2bfloat16(v1 - __bfloat162float(h1));
                    size_t o = gr * ldc + col;
                    *(__nv_bfloat162*)(Fhi + o) = hp;
                    *(__nv_bfloat162*)(Flo + o) = lp;
                }
            }
        } else {
            float s0 = 1.f, s1 = 1.f;
            if (epi == 2) {
                s0 = 1.0f / scale[(size_t)b * mpb + row0];
                s1 = 1.0f / scale[(size_t)b * mpb + row0 + 8];
            }
            float* Cb = C + (size_t)b * c_bs;
            #pragma unroll
            for (int fn = 0; fn < 8; fn++) {
                const int col = bn + wn * 64 + fn * 8 + fc;
                float2 v0, v1;
                v0.x = acc[fm][fn][0] * s0; v0.y = acc[fm][fn][1] * s0;
                v1.x = acc[fm][fn][2] * s1; v1.y = acc[fm][fn][3] * s1;
                *(float2*)(Cb + (size_t)row0 * ldc + col) = v0;
                *(float2*)(Cb + (size_t)(row0 + 8) * ldc + col) = v1;
            }
        }
    }
}

// ---------------------------------------------------------------------------
// Elementwise / transform kernels
// ---------------------------------------------------------------------------
__global__ void split_kernel(const float* __restrict__ in, bf16* __restrict__ hi,
                             bf16* __restrict__ lo, size_t n4) {
    size_t i = (size_t)blockIdx.x * 256 + threadIdx.x;
    if (i >= n4) return;
    float4 v = ((const float4*)in)[i];
    float vv[4] = {v.x, v.y, v.z, v.w};
    __nv_bfloat162 h01, h23, l01, l23;
    bf16 h[4], l[4];
    #pragma unroll
    for (int j = 0; j < 4; j++) {
        h[j] = __float2bfloat16(vv[j]);
        l[j] = __float2bfloat16(vv[j] - __bfloat162float(h[j]));
    }
    h01.x = h[0]; h01.y = h[1]; h23.x = h[2]; h23.y = h[3];
    l01.x = l[0]; l01.y = l[1]; l23.x = l[2]; l23.y = l[3];
    ((__nv_bfloat162*)hi)[2 * i] = h01; ((__nv_bfloat162*)hi)[2 * i + 1] = h23;
    ((__nv_bfloat162*)lo)[2 * i] = l01; ((__nv_bfloat162*)lo)[2 * i + 1] = l23;
}

__global__ void transpose_split_kernel(const float* __restrict__ in, bf16* __restrict__ ohi,
                                       bf16* __restrict__ olo, int R, int C,
                                       size_t ibs, size_t obs) {
    __shared__ float tile[32][33];
    const float* ip = in + (size_t)blockIdx.z * ibs;
    int c0 = blockIdx.x * 32, r0 = blockIdx.y * 32;
    int tx = threadIdx.x, ty = threadIdx.y;
    #pragma unroll
    for (int i = ty; i < 32; i += 8)
        tile[i][tx] = ip[(size_t)(r0 + i) * C + c0 + tx];
    __syncthreads();
    size_t ob = (size_t)blockIdx.z * obs;
    #pragma unroll
    for (int i = ty; i < 32; i += 8) {
        float v = tile[tx][i];
        bf16 h = __float2bfloat16(v);
        size_t o = ob + (size_t)(c0 + i) * R + r0 + tx;
        ohi[o] = h;
        olo[o] = __float2bfloat16(v - __bfloat162float(h));
    }
}

__global__ void transpose_f32_kernel(const float* __restrict__ in, float* __restrict__ out) {
    __shared__ float tile[32][33];
    const float* ip = in + (size_t)blockIdx.z * (LL * LL);
    float* op = out + (size_t)blockIdx.z * (LL * LL);
    int c0 = blockIdx.x * 32, r0 = blockIdx.y * 32;
    int tx = threadIdx.x, ty = threadIdx.y;
    #pragma unroll
    for (int i = ty; i < 32; i += 8)
        tile[i][tx] = ip[(size_t)(r0 + i) * LL + c0 + tx];
    __syncthreads();
    #pragma unroll
    for (int i = ty; i < 32; i += 8)
        op[(size_t)(c0 + i) * LL + r0 + tx] = tile[tx][i];
}

__global__ void rowmax_kernel(const float* __restrict__ E, float* __restrict__ out) {
    size_t row = blockIdx.x;
    float4 v = ((const float4*)(E + row * LL))[threadIdx.x];
    float m = fmaxf(fmaxf(v.x, v.y), fmaxf(v.z, v.w));
    #pragma unroll
    for (int o = 16; o; o >>= 1) m = fmaxf(m, __shfl_xor_sync(~0u, m, o));
    __shared__ float red[8];
    if ((threadIdx.x & 31) == 0) red[threadIdx.x >> 5] = m;
    __syncthreads();
    if (threadIdx.x == 0) {
        float M = red[0];
        #pragma unroll
        for (int i = 1; i < 8; i++) M = fmaxf(M, red[i]);
        out[row] = M;
    }
}

__global__ void expsplit_kernel(const float* __restrict__ E, const float* __restrict__ rmax,
                                bf16* __restrict__ thi, bf16* __restrict__ tlo,
                                float* __restrict__ rsum) {
    size_t row = blockIdx.x;
    float M = rmax[row];
    float4 v = ((const float4*)(E + row * LL))[threadIdx.x];
    float t0 = __expf(v.x - M), t1 = __expf(v.y - M);
    float t2 = __expf(v.z - M), t3 = __expf(v.w - M);
    float tv[4] = {t0, t1, t2, t3};
    __nv_bfloat162 h01, h23, l01, l23;
    bf16 h[4], l[4];
    #pragma unroll
    for (int j = 0; j < 4; j++) {
        h[j] = __float2bfloat16(tv[j]);
        l[j] = __float2bfloat16(tv[j] - __bfloat162float(h[j]));
    }
    h01.x = h[0]; h01.y = h[1]; h23.x = h[2]; h23.y = h[3];
    l01.x = l[0]; l01.y = l[1]; l23.x = l[2]; l23.y = l[3];
    size_t p2 = row * 512 + (size_t)threadIdx.x * 2;
    ((__nv_bfloat162*)thi)[p2] = h01; ((__nv_bfloat162*)thi)[p2 + 1] = h23;
    ((__nv_bfloat162*)tlo)[p2] = l01; ((__nv_bfloat162*)tlo)[p2 + 1] = l23;
    float s = (t0 + t1) + (t2 + t3);
    #pragma unroll
    for (int o = 16; o; o >>= 1) s += __shfl_xor_sync(~0u, s, o);
    __shared__ float red[8];
    if ((threadIdx.x & 31) == 0) red[threadIdx.x >> 5] = s;
    __syncthreads();
    if (threadIdx.x == 0) {
        float S = 0.f;
        #pragma unroll
        for (int i = 0; i < 8; i++) S += red[i];
        rsum[row] = S;
    }
}

// ---------------------------------------------------------------------------
#define SYM(p, s) do { void* _t; cudaGetSymbolAddress(&_t, s); p = decltype(p)(_t); } while (0)

extern "C" void kernel_launch(void* const* d_in, const int* in_sizes, int n_in,
                              void* d_out, int out_size) {
    const float* P   = (const float*)d_in[0];
    const float* Hyp = (const float*)d_in[1];
    const float* W   = (const float*)d_in[2];
    float* out = (float*)d_out;

    bf16 *Xph, *Xpl, *Xhh, *Xhl, *Wth, *Wtl, *Fph, *Fpl, *Fhh, *Fhl;
    bf16 *Hth, *Htl, *Pth, *Ptl, *Trh, *Trl, *Tch, *Tcl;
    float *E, *Et, *rmax, *rsum, *cmax, *csum;
    SYM(Xph, g_Xp_hi); SYM(Xpl, g_Xp_lo); SYM(Xhh, g_Xh_hi); SYM(Xhl, g_Xh_lo);
    SYM(Wth, g_Wt_hi); SYM(Wtl, g_Wt_lo);
    SYM(Fph, g_Fp_hi); SYM(Fpl, g_Fp_lo); SYM(Fhh, g_Fh_hi); SYM(Fhl, g_Fh_lo);
    SYM(Hth, g_Ht_hi); SYM(Htl, g_Ht_lo); SYM(Pth, g_Pt_hi); SYM(Ptl, g_Pt_lo);
    SYM(Trh, g_Tr_hi); SYM(Trl, g_Tr_lo); SYM(Tch, g_Tc_hi); SYM(Tcl, g_Tc_lo);
    SYM(E, g_E); SYM(Et, g_Et);
    SYM(rmax, g_rowmax); SYM(rsum, g_rowsum); SYM(cmax, g_colmax); SYM(csum, g_colsum);

    dim3 t256(256), t32x8(32, 8);

    // input conversions
    split_kernel<<<8192, t256>>>(P, Xph, Xpl, NXD / 4);
    split_kernel<<<8192, t256>>>(Hyp, Xhh, Xhl, NXD / 4);
    transpose_split_kernel<<<dim3(8, 8, 1), t32x8>>>(W, Wth, Wtl, DD, HH, 0, 0);
    transpose_split_kernel<<<dim3(8, 32, NB), t32x8>>>(Hyp, Hth, Htl, LL, DD,
                                                       (size_t)LL * DD, (size_t)LL * DD);
    transpose_split_kernel<<<dim3(8, 32, NB), t32x8>>>(P, Pth, Ptl, LL, DD,
                                                       (size_t)LL * DD, (size_t)LL * DD);

    // proj: F = tanh(X @ W)  (M=32768 flattened, N=256, K=256)
    gemm_split<<<dim3(256, 2, 1), t256>>>(Xph, Xpl, 0, DD, Wth, Wtl, 0, DD, DD, 1,
                                          nullptr, 0, HH, nullptr, 0, Fph, Fpl);
    gemm_split<<<dim3(256, 2, 1), t256>>>(Xhh, Xhl, 0, DD, Wth, Wtl, 0, DD, DD, 1,
                                          nullptr, 0, HH, nullptr, 0, Fhh, Fhl);

    // eij: E[b] = Fp[b] @ Fh[b]^T  (M=1024, N=1024, K=256)
    gemm_split<<<dim3(8, 8, NB), t256>>>(Fph, Fpl, (size_t)LL * DD, HH,
                                         Fhh, Fhl, (size_t)LL * DD, HH, HH, 0,
                                         E, (size_t)LL * LL, LL, nullptr, 0, nullptr, nullptr);

    // transpose + softmax stats + exp-split
    transpose_f32_kernel<<<dim3(32, 32, NB), t32x8>>>(E, Et);
    rowmax_kernel<<<NB * LL, t256>>>(E, rmax);
    rowmax_kernel<<<NB * LL, t256>>>(Et, cmax);
    expsplit_kernel<<<NB * LL, t256>>>(E, rmax, Trh, Trl, rsum);
    expsplit_kernel<<<NB * LL, t256>>>(Et, cmax, Tch, Tcl, csum);

    // betas: (exp(E-rowmax) @ Hyp) / rowsum   (M=1024, N=256, K=1024)
    gemm_split<<<dim3(8, 2, NB), t256>>>(Trh, Trl, (size_t)LL * LL, LL,
                                         Hth, Htl, (size_t)DD * LL, LL, LL, 2,
                                         out, (size_t)LL * DD, DD, rsum, LL, nullptr, nullptr);
    // alphas: (exp(Et-colmax) @ Prem) / colsum
    gemm_split<<<dim3(8, 2, NB), t256>>>(Tch, Tcl, (size_t)LL * LL, LL,
                                         Pth, Ptl, (size_t)DD * LL, LL, LL, 2,
                                         out + (size_t)NB * LL * DD, (size_t)LL * DD, DD,
                                         csum, LL, nullptr, nullptr);
}

// round 7
// speedup vs baseline: 2.8542x; 1.1943x over previous
#include <cuda_runtime.h>
#include <cuda_bf16.h>
#include <math.h>
#include <stdint.h>

#define NB 32
#define LL 1024
#define DD 256
#define HH 256
typedef __nv_bfloat16 bf16;

#define NXD ((size_t)NB * LL * DD)
#define NE  ((size_t)NB * LL * LL)

// ---------------------------------------------------------------------------
// Device scratch
// ---------------------------------------------------------------------------
__device__ __align__(256) bf16 g_Xp_hi[NXD], g_Xp_lo[NXD];
__device__ __align__(256) bf16 g_Xh_hi[NXD], g_Xh_lo[NXD];
__device__ __align__(256) bf16 g_Wt_hi[DD * HH], g_Wt_lo[DD * HH];
__device__ __align__(256) bf16 g_Fp_hi[NXD], g_Fp_lo[NXD];
__device__ __align__(256) bf16 g_Fh_hi[NXD], g_Fh_lo[NXD];
__device__ __align__(256) bf16 g_Ht_hi[NXD], g_Ht_lo[NXD];
__device__ __align__(256) bf16 g_Pt_hi[NXD], g_Pt_lo[NXD];
__device__ __align__(256) float g_E[NE];
__device__ __align__(256) bf16 g_Tr_hi[NE], g_Tr_lo[NE];
__device__ __align__(256) float g_rowmax[NB * LL], g_rowsum[NB * LL], g_colsum[NB * LL];
__device__ __align__(256) float g_Mb[NB];

// ---------------------------------------------------------------------------
// helpers
// ---------------------------------------------------------------------------
__device__ __forceinline__ uint32_t smem_u32(const void* p) {
    uint32_t a;
    asm("{ .reg .u64 t; cvta.to.shared.u64 t, %1; cvt.u32.u64 %0, t; }" : "=r"(a) : "l"(p));
    return a;
}
__device__ __forceinline__ void cp_async16(uint32_t dst, const void* src) {
    asm volatile("cp.async.cg.shared.global [%0], [%1], 16;" :: "r"(dst), "l"(src));
}
__device__ __forceinline__ void ldsm4(uint32_t& r0, uint32_t& r1, uint32_t& r2,
                                      uint32_t& r3, uint32_t addr) {
    asm volatile("ldmatrix.sync.aligned.m8n8.x4.shared.b16 {%0,%1,%2,%3}, [%4];"
                 : "=r"(r0), "=r"(r1), "=r"(r2), "=r"(r3) : "r"(addr));
}
__device__ __forceinline__ void ldsm4t(uint32_t& r0, uint32_t& r1, uint32_t& r2,
                                       uint32_t& r3, uint32_t addr) {
    asm volatile("ldmatrix.sync.aligned.m8n8.x4.trans.shared.b16 {%0,%1,%2,%3}, [%4];"
                 : "=r"(r0), "=r"(r1), "=r"(r2), "=r"(r3) : "r"(addr));
}
__device__ __forceinline__ void mma_bf16(float* c, const uint32_t* a, uint32_t b0, uint32_t b1) {
    asm volatile(
        "mma.sync.aligned.m16n8k16.row.col.f32.bf16.bf16.f32 "
        "{%0,%1,%2,%3}, {%4,%5,%6,%7}, {%8,%9}, {%0,%1,%2,%3};"
        : "+f"(c[0]), "+f"(c[1]), "+f"(c[2]), "+f"(c[3])
        : "r"(a[0]), "r"(a[1]), "r"(a[2]), "r"(a[3]), "r"(b0), "r"(b1));
}
__device__ __forceinline__ void atomicMaxF(float* a, float v) {
    if (v >= 0.f) atomicMax((int*)a, __float_as_int(v));
    else          atomicMin((unsigned int*)a, __float_as_uint(v));
}

// ---------------------------------------------------------------------------
// Split-bf16 warp-MMA GEMM (normal A): C[m,n] = sum_k A[m,k]*B[n,k]
// 3 passes (hh, h*Blo, Alo*h) in register acc. CTA 128x128, BK=32, cp.async
// double-buffered. epi: 0 fp32 C (+opt rowmax atomics); 1 tanh->split bf16;
// 2 scale 1/scale[b*mpb+m].
// ---------------------------------------------------------------------------
__global__ __launch_bounds__(256) void gemm_split(
    const bf16* __restrict__ Ahi, const bf16* __restrict__ Alo, size_t a_bs, int lda,
    const bf16* __restrict__ Bhi, const bf16* __restrict__ Blo, size_t b_bs, int ldb,
    int K, int epi,
    float* __restrict__ C, size_t c_bs, int ldc,
    const float* __restrict__ scale, int mpb,
    bf16* __restrict__ Fhi, bf16* __restrict__ Flo,
    float* __restrict__ rmaxAt)
{
    __shared__ __align__(16) uint8_t sm[2 * 20480];   // [stage][A 10240 | B 10240]
    const uint32_t smb = smem_u32(sm);
    const int tid = threadIdx.x, lane = tid & 31, wid = tid >> 5;
    const int wm = wid & 3, wn = wid >> 2;
    const int bm = blockIdx.x * 128, bn = blockIdx.y * 128, b = blockIdx.z;
    const int nk = K >> 5, nch = 3 * nk;

    const int r0s = tid >> 2,          kv0 = (tid & 3) * 8;
    const int r1s = (tid + 256) >> 2,  kv1 = ((tid + 256) & 3) * 8;

    auto issue = [&](int ch, int st) {
        const int pass = ch / nk;
        const int k0 = (ch - pass * nk) << 5;
        const bf16* Ap = (pass == 2 ? Alo : Ahi) + (size_t)b * a_bs;
        const bf16* Bp = (pass == 1 ? Blo : Bhi) + (size_t)b * b_bs;
        uint32_t da = smb + (uint32_t)st * 20480;
        uint32_t db = da + 10240;
        cp_async16(da + r0s * 80 + kv0 * 2, Ap + (size_t)(bm + r0s) * lda + k0 + kv0);
        cp_async16(da + r1s * 80 + kv1 * 2, Ap + (size_t)(bm + r1s) * lda + k0 + kv1);
        cp_async16(db + r0s * 80 + kv0 * 2, Bp + (size_t)(bn + r0s) * ldb + k0 + kv0);
        cp_async16(db + r1s * 80 + kv1 * 2, Bp + (size_t)(bn + r1s) * ldb + k0 + kv1);
        asm volatile("cp.async.commit_group;");
    };

    float acc[2][8][4] = {};
    issue(0, 0);
    for (int ch = 0; ch < nch; ch++) {
        const int st = ch & 1;
        if (ch + 1 < nch) { issue(ch + 1, st ^ 1); asm volatile("cp.async.wait_group 1;"); }
        else              { asm volatile("cp.async.wait_group 0;"); }
        __syncthreads();
        const uint32_t sAb = smb + (uint32_t)st * 20480;
        const uint32_t sBb = sAb + 10240;
        #pragma unroll
        for (int ks = 0; ks < 2; ks++) {
            const uint32_t colb = (uint32_t)(ks * 16 + (lane >> 4) * 8) * 2;
            uint32_t a[2][4];
            #pragma unroll
            for (int fm = 0; fm < 2; fm++) {
                uint32_t ad = sAb + (uint32_t)(wm * 32 + fm * 16 + (lane & 15)) * 80 + colb;
                ldsm4(a[fm][0], a[fm][1], a[fm][2], a[fm][3], ad);
            }
            uint32_t bb[4][4];
            #pragma unroll
            for (int fn = 0; fn < 4; fn++) {
                uint32_t bd = sBb + (uint32_t)(wn * 64 + fn * 16 + (lane & 15)) * 80 + colb;
                ldsm4(bb[fn][0], bb[fn][1], bb[fn][2], bb[fn][3], bd);
            }
            #pragma unroll
            for (int fm = 0; fm < 2; fm++)
                #pragma unroll
                for (int fn = 0; fn < 4; fn++) {
                    mma_bf16(acc[fm][fn * 2],     a[fm], bb[fn][0], bb[fn][2]);
                    mma_bf16(acc[fm][fn * 2 + 1], a[fm], bb[fn][1], bb[fn][3]);
                }
        }
        __syncthreads();
    }

    const int fr = lane >> 2;
    const int fc = (lane & 3) * 2;
    if (rmaxAt) {
        #pragma unroll
        for (int fm = 0; fm < 2; fm++)
            #pragma unroll
            for (int half = 0; half < 2; half++) {
                float m = -INFINITY;
                #pragma unroll
                for (int fn = 0; fn < 8; fn++) {
                    m = fmaxf(m, acc[fm][fn][half * 2]);
                    m = fmaxf(m, acc[fm][fn][half * 2 + 1]);
                }
                m = fmaxf(m, __shfl_xor_sync(~0u, m, 1));
                m = fmaxf(m, __shfl_xor_sync(~0u, m, 2));
                if ((lane & 3) == 0)
                    atomicMaxF(rmaxAt + (size_t)b * mpb + bm + wm * 32 + fm * 16 + fr + half * 8, m);
            }
    }
    #pragma unroll
    for (int fm = 0; fm < 2; fm++) {
        const int row0 = bm + wm * 32 + fm * 16 + fr;
        if (epi == 1) {
            #pragma unroll
            for (int half = 0; half < 2; half++) {
                const size_t gr = (size_t)(row0 + half * 8);
                #pragma unroll
                for (int fn = 0; fn < 8; fn++) {
                    const int col = bn + wn * 64 + fn * 8 + fc;
                    float v0 = tanhf(acc[fm][fn][half * 2]);
                    float v1 = tanhf(acc[fm][fn][half * 2 + 1]);
                    bf16 h0 = __float2bfloat16(v0), h1 = __float2bfloat16(v1);
                    __nv_bfloat162 hp, lp;
                    hp.x = h0; hp.y = h1;
                    lp.x = __float2bfloat16(v0 - __bfloat162float(h0));
                    lp.y = __float2bfloat16(v1 - __bfloat162float(h1));
                    size_t o = gr * ldc + col;
                    *(__nv_bfloat162*)(Fhi + o) = hp;
                    *(__nv_bfloat162*)(Flo + o) = lp;
                }
            }
        } else {
            float s0 = 1.f, s1 = 1.f;
            if (epi == 2) {
                s0 = 1.0f / scale[(size_t)b * mpb + row0];
                s1 = 1.0f / scale[(size_t)b * mpb + row0 + 8];
            }
            float* Cb = C + (size_t)b * c_bs;
            #pragma unroll
            for (int fn = 0; fn < 8; fn++) {
                const int col = bn + wn * 64 + fn * 8 + fc;
                float2 v0, v1;
                v0.x = acc[fm][fn][0] * s0; v0.y = acc[fm][fn][1] * s0;
                v1.x = acc[fm][fn][2] * s1; v1.y = acc[fm][fn][3] * s1;
                *(float2*)(Cb + (size_t)row0 * ldc + col) = v0;
                *(float2*)(Cb + (size_t)(row0 + 8) * ldc + col) = v1;
            }
        }
    }
}

// ---------------------------------------------------------------------------
// Trans-A variant (alphas): C[m,n] = sum_k A[k,m]*B[n,k]  (A read transposed
// via ldmatrix.trans). A tile [32k x 128m] pitch 272B, B tile [128n x 32k]
// pitch 80B. Scaled fp32 output.
// ---------------------------------------------------------------------------
__global__ __launch_bounds__(256) void gemm_splitT(
    const bf16* __restrict__ Ahi, const bf16* __restrict__ Alo, size_t a_bs, int lda,
    const bf16* __restrict__ Bhi, const bf16* __restrict__ Blo, size_t b_bs, int ldb,
    int K,
    float* __restrict__ C, size_t c_bs, int ldc,
    const float* __restrict__ scale, int mpb)
{
    __shared__ __align__(16) uint8_t sm[2 * 18944];   // [stage][A 8704 | B 10240]
    const uint32_t smb = smem_u32(sm);
    const int tid = threadIdx.x, lane = tid & 31, wid = tid >> 5;
    const int wm = wid & 3, wn = wid >> 2;
    const int bm = blockIdx.x * 128, bn = blockIdx.y * 128, b = blockIdx.z;
    const int nk = K >> 5, nch = 3 * nk;

    // A: 32 k-rows x 128 m-cols = 512 chunks -> 2 per thread
    const int ar  = tid >> 4,          akv = (tid & 15) * 8;
    const int r0s = tid >> 2,          kv0 = (tid & 3) * 8;
    const int r1s = (tid + 256) >> 2,  kv1 = ((tid + 256) & 3) * 8;

    auto issue = [&](int ch, int st) {
        const int pass = ch / nk;
        const int k0 = (ch - pass * nk) << 5;
        const bf16* Ap = (pass == 2 ? Alo : Ahi) + (size_t)b * a_bs;
        const bf16* Bp = (pass == 1 ? Blo : Bhi) + (size_t)b * b_bs;
        uint32_t da = smb + (uint32_t)st * 18944;
        uint32_t db = da + 8704;
        cp_async16(da + ar * 272 + akv * 2,
                   Ap + (size_t)(k0 + ar) * lda + bm + akv);
        cp_async16(da + (ar + 16) * 272 + akv * 2,
                   Ap + (size_t)(k0 + ar + 16) * lda + bm + akv);
        cp_async16(db + r0s * 80 + kv0 * 2, Bp + (size_t)(bn + r0s) * ldb + k0 + kv0);
        cp_async16(db + r1s * 80 + kv1 * 2, Bp + (size_t)(bn + r1s) * ldb + k0 + kv1);
        asm volatile("cp.async.commit_group;");
    };

    float acc[2][8][4] = {};
    issue(0, 0);
    for (int ch = 0; ch < nch; ch++) {
        const int st = ch & 1;
        if (ch + 1 < nch) { issue(ch + 1, st ^ 1); asm volatile("cp.async.wait_group 1;"); }
        else              { asm volatile("cp.async.wait_group 0;"); }
        __syncthreads();
        const uint32_t sAb = smb + (uint32_t)st * 18944;
        const uint32_t sBb = sAb + 8704;
        #pragma unroll
        for (int ks = 0; ks < 2; ks++) {
            uint32_t a[2][4];
            #pragma unroll
            for (int fm = 0; fm < 2; fm++) {
                uint32_t ad = sAb
                    + (uint32_t)(ks * 16 + ((lane >> 4) << 3) + (lane & 7)) * 272
                    + (uint32_t)(wm * 32 + fm * 16 + ((lane >> 3) & 1) * 8) * 2;
                ldsm4t(a[fm][0], a[fm][1], a[fm][2], a[fm][3], ad);
            }
            const uint32_t colb = (uint32_t)(ks * 16 + (lane >> 4) * 8) * 2;
            uint32_t bb[4][4];
            #pragma unroll
            for (int fn = 0; fn < 4; fn++) {
                uint32_t bd = sBb + (uint32_t)(wn * 64 + fn * 16 + (lane & 15)) * 80 + colb;
                ldsm4(bb[fn][0], bb[fn][1], bb[fn][2], bb[fn][3], bd);
            }
            #pragma unroll
            for (int fm = 0; fm < 2; fm++)
                #pragma unroll
                for (int fn = 0; fn < 4; fn++) {
                    mma_bf16(acc[fm][fn * 2],     a[fm], bb[fn][0], bb[fn][2]);
                    mma_bf16(acc[fm][fn * 2 + 1], a[fm], bb[fn][1], bb[fn][3]);
                }
        }
        __syncthreads();
    }

    const int fr = lane >> 2;
    const int fc = (lane & 3) * 2;
    #pragma unroll
    for (int fm = 0; fm < 2; fm++) {
        const int row0 = bm + wm * 32 + fm * 16 + fr;
        float s0 = 1.0f / scale[(size_t)b * mpb + row0];
        float s1 = 1.0f / scale[(size_t)b * mpb + row0 + 8];
        float* Cb = C + (size_t)b * c_bs;
        #pragma unroll
        for (int fn = 0; fn < 8; fn++) {
            const int col = bn + wn * 64 + fn * 8 + fc;
            float2 v0, v1;
            v0.x = acc[fm][fn][0] * s0; v0.y = acc[fm][fn][1] * s0;
            v1.x = acc[fm][fn][2] * s1; v1.y = acc[fm][fn][3] * s1;
            *(float2*)(Cb + (size_t)row0 * ldc + col) = v0;
            *(float2*)(Cb + (size_t)(row0 + 8) * ldc + col) = v1;
        }
    }
}

// ---------------------------------------------------------------------------
// Elementwise / transform kernels
// ---------------------------------------------------------------------------
__global__ void split_kernel(const float* __restrict__ in, bf16* __restrict__ hi,
                             bf16* __restrict__ lo, size_t n4) {
    size_t i = (size_t)blockIdx.x * 256 + threadIdx.x;
    if (i >= n4) return;
    float4 v = ((const float4*)in)[i];
    float vv[4] = {v.x, v.y, v.z, v.w};
    bf16 h[4];
    union { __nv_bfloat162 b2[2]; uint2 u; } uh, ul;
    #pragma unroll
    for (int j = 0; j < 4; j++) h[j] = __float2bfloat16(vv[j]);
    uh.b2[0].x = h[0]; uh.b2[0].y = h[1]; uh.b2[1].x = h[2]; uh.b2[1].y = h[3];
    ul.b2[0].x = __float2bfloat16(vv[0] - __bfloat162float(h[0]));
    ul.b2[0].y = __float2bfloat16(vv[1] - __bfloat162float(h[1]));
    ul.b2[1].x = __float2bfloat16(vv[2] - __bfloat162float(h[2]));
    ul.b2[1].y = __float2bfloat16(vv[3] - __bfloat162float(h[3]));
    ((uint2*)hi)[i] = uh.u;
    ((uint2*)lo)[i] = ul.u;
}

// transpose + split; if scaled, multiply input row p by er[p]=exp(rowmax-Mb)
__global__ void transpose_split_kernel(const float* __restrict__ in, bf16* __restrict__ ohi,
                                       bf16* __restrict__ olo, int R, int C,
                                       size_t ibs, size_t obs, int scaled) {
    __shared__ float tile[32][33];
    const int bz = blockIdx.z;
    const float* ip = in + (size_t)bz * ibs;
    int c0 = blockIdx.x * 32, r0 = blockIdx.y * 32;
    int tx = threadIdx.x, ty = threadIdx.y;
    #pragma unroll
    for (int i = ty; i < 32; i += 8)
        tile[i][tx] = ip[(size_t)(r0 + i) * C + c0 + tx];
    __syncthreads();
    float er = 1.f;
    if (scaled) er = __expf(g_rowmax[(size_t)bz * LL + r0 + tx] - g_Mb[bz]);
    size_t ob = (size_t)bz * obs;
    #pragma unroll
    for (int i = ty; i < 32; i += 8) {
        float v = tile[tx][i] * er;
        bf16 h = __float2bfloat16(v);
        size_t o = ob + (size_t)(c0 + i) * R + r0 + tx;
        ohi[o] = h;
        olo[o] = __float2bfloat16(v - __bfloat162float(h));
    }
}

__global__ void initstats_kernel() {
    int i = blockIdx.x * 256 + threadIdx.x;
    if (i < NB * LL) { g_rowmax[i] = -INFINITY; g_colsum[i] = 0.f; }
}

__global__ void mbmax_kernel() {
    const int b = blockIdx.x, t = threadIdx.x;
    float4 v = ((const float4*)(g_rowmax + (size_t)b * LL))[t];
    float m = fmaxf(fmaxf(v.x, v.y), fmaxf(v.z, v.w));
    #pragma unroll
    for (int o = 16; o; o >>= 1) m = fmaxf(m, __shfl_xor_sync(~0u, m, o));
    __shared__ float red[8];
    if ((t & 31) == 0) red[t >> 5] = m;
    __syncthreads();
    if (t == 0) {
        float M = red[0];
        #pragma unroll
        for (int i = 1; i < 8; i++) M = fmaxf(M, red[i]);
        g_Mb[b] = M;
    }
}

// Single fused pass over E: Tr = split(exp(E-rowmax)), rowsum direct,
// csum'[q] += er[p]*tr[p,q] via atomics.
__global__ __launch_bounds__(256) void dual_exp_kernel() {
    const int b = blockIdx.y;
    const int r0 = blockIdx.x * 64;
    const int w = threadIdx.x >> 5, lane = threadIdx.x & 31;
    const float Mb = g_Mb[b];
    const float* Eb = g_E + (size_t)b * LL * LL;
    bf16* Th = g_Tr_hi + (size_t)b * LL * LL;
    bf16* Tl = g_Tr_lo + (size_t)b * LL * LL;
    float cs[32];
    #pragma unroll
    for (int k = 0; k < 32; k++) cs[k] = 0.f;
    #pragma unroll 1
    for (int j = 0; j < 8; j++) {
        const int row = r0 + w * 8 + j;
        const float rm = g_rowmax[(size_t)b * LL + row];
        const float er = __expf(rm - Mb);
        const float4* src = (const float4*)(Eb + (size_t)row * LL);
        float s = 0.f;
        #pragma unroll
        for (int k = 0; k < 8; k++) {
            float4 v = src[lane + 32 * k];
            float t0 = __expf(v.x - rm), t1 = __expf(v.y - rm);
            float t2 = __expf(v.z - rm), t3 = __expf(v.w - rm);
            s += (t0 + t1) + (t2 + t3);
            cs[k * 4 + 0] += er * t0; cs[k * 4 + 1] += er * t1;
            cs[k * 4 + 2] += er * t2; cs[k * 4 + 3] += er * t3;
            bf16 h0 = __float2bfloat16(t0), h1 = __float2bfloat16(t1);
            bf16 h2 = __float2bfloat16(t2), h3 = __float2bfloat16(t3);
            union { __nv_bfloat162 b2[2]; uint2 u; } uh, ul;
            uh.b2[0].x = h0; uh.b2[0].y = h1; uh.b2[1].x = h2; uh.b2[1].y = h3;
            ul.b2[0].x = __float2bfloat16(t0 - __bfloat162float(h0));
            ul.b2[0].y = __float2bfloat16(t1 - __bfloat162float(h1));
            ul.b2[1].x = __float2bfloat16(t2 - __bfloat162float(h2));
            ul.b2[1].y = __float2bfloat16(t3 - __bfloat162float(h3));
            size_t o = (size_t)row * LL + 4 * (lane + 32 * k);
            *(uint2*)(Th + o) = uh.u;
            *(uint2*)(Tl + o) = ul.u;
        }
        #pragma unroll
        for (int o = 16; o; o >>= 1) s += __shfl_xor_sync(~0u, s, o);
        if (lane == 0) g_rowsum[(size_t)b * LL + row] = s;
    }
    #pragma unroll
    for (int k = 0; k < 8; k++)
        #pragma unroll
        for (int j2 = 0; j2 < 4; j2++)
            atomicAdd(g_colsum + (size_t)b * LL + 4 * (lane + 32 * k) + j2, cs[k * 4 + j2]);
}

// ---------------------------------------------------------------------------
#define SYM(p, s) do { void* _t; cudaGetSymbolAddress(&_t, s); p = decltype(p)(_t); } while (0)

extern "C" void kernel_launch(void* const* d_in, const int* in_sizes, int n_in,
                              void* d_out, int out_size) {
    const float* P   = (const float*)d_in[0];
    const float* Hyp = (const float*)d_in[1];
    const float* W   = (const float*)d_in[2];
    float* out = (float*)d_out;

    bf16 *Xph, *Xpl, *Xhh, *Xhl, *Wth, *Wtl, *Fph, *Fpl, *Fhh, *Fhl;
    bf16 *Hth, *Htl, *Pth, *Ptl, *Trh, *Trl;
    float *E, *rmax, *rsum, *csum;
    SYM(Xph, g_Xp_hi); SYM(Xpl, g_Xp_lo); SYM(Xhh, g_Xh_hi); SYM(Xhl, g_Xh_lo);
    SYM(Wth, g_Wt_hi); SYM(Wtl, g_Wt_lo);
    SYM(Fph, g_Fp_hi); SYM(Fpl, g_Fp_lo); SYM(Fhh, g_Fh_hi); SYM(Fhl, g_Fh_lo);
    SYM(Hth, g_Ht_hi); SYM(Htl, g_Ht_lo); SYM(Pth, g_Pt_hi); SYM(Ptl, g_Pt_lo);
    SYM(Trh, g_Tr_hi); SYM(Trl, g_Tr_lo);
    SYM(E, g_E);
    SYM(rmax, g_rowmax); SYM(rsum, g_rowsum); SYM(csum, g_colsum);

    dim3 t256(256), t32x8(32, 8);

    // input conversions
    split_kernel<<<8192, t256>>>(P, Xph, Xpl, NXD / 4);
    split_kernel<<<8192, t256>>>(Hyp, Xhh, Xhl, NXD / 4);
    transpose_split_kernel<<<dim3(8, 8, 1), t32x8>>>(W, Wth, Wtl, DD, HH, 0, 0, 0);
    transpose_split_kernel<<<dim3(8, 32, NB), t32x8>>>(Hyp, Hth, Htl, LL, DD,
                                                       (size_t)LL * DD, (size_t)LL * DD, 0);

    // proj: F = tanh(X @ W)
    gemm_split<<<dim3(256, 2, 1), t256>>>(Xph, Xpl, 0, DD, Wth, Wtl, 0, DD, DD, 1,
                                          nullptr, 0, HH, nullptr, 0, Fph, Fpl, nullptr);
    gemm_split<<<dim3(256, 2, 1), t256>>>(Xhh, Xhl, 0, DD, Wth, Wtl, 0, DD, DD, 1,
                                          nullptr, 0, HH, nullptr, 0, Fhh, Fhl, nullptr);

    // stats init + eij (E + rowmax atomics fused)
    initstats_kernel<<<128, t256>>>();
    gemm_split<<<dim3(8, 8, NB), t256>>>(Fph, Fpl, (size_t)LL * DD, HH,
                                         Fhh, Fhl, (size_t)LL * DD, HH, HH, 0,
                                         E, (size_t)LL * LL, LL, nullptr, LL,
                                         nullptr, nullptr, rmax);
    mbmax_kernel<<<NB, t256>>>();

    // fused exp/split/rowsum/colsum' pass (single read of E)
    dual_exp_kernel<<<dim3(16, NB), t256>>>();

    // Pt' = transpose(er[p] * P[p,d])
    transpose_split_kernel<<<dim3(8, 32, NB), t32x8>>>(P, Pth, Ptl, LL, DD,
                                                       (size_t)LL * DD, (size_t)LL * DD, 1);

    // betas = (Tr @ Ht) / rowsum
    gemm_split<<<dim3(8, 2, NB), t256>>>(Trh, Trl, (size_t)LL * LL, LL,
                                         Hth, Htl, (size_t)DD * LL, LL, LL, 2,
                                         out, (size_t)LL * DD, DD, rsum, LL,
                                         nullptr, nullptr, nullptr);
    // alphas = (Tr^T @ Pt') / csum'
    gemm_splitT<<<dim3(8, 2, NB), t256>>>(Trh, Trl, (size_t)LL * LL, LL,
                                          Pth, Ptl, (size_t)DD * LL, LL, LL,
                                          out + (size_t)NB * LL * DD, (size_t)LL * DD, DD,
                                          csum, LL);
}